// round 7
// baseline (speedup 1.0000x reference)
#include <cuda_runtime.h>
#include <cuda_bf16.h>
#include <stdint.h>

// ---------------- problem constants ----------------
#define BB 32
#define CC 128
#define NN 16384
#define KK 64
#define TILE_N 64
#define STRIPES 4
#define NT ((NN / STRIPES) / TILE_N)   // 64 tiles per CTA
#define NTHREADS 384

// ---------------- smem layout ----------------
#define PX  72       // x tile pitch (elems); 144 B rows
#define PBX 144
#define PW  136
#define PBW 272
#define PA  72
#define PBA 144
#define PL  68       // logits pitch (fp32)

#define OFF_XHI0   0u        // [144 c-rows][72] bf16 (rows 128.. ones/zeros)
#define OFF_XLO0   20736u
#define OFF_XHI1   41472u
#define OFF_XLO1   62208u
#define OFF_WHI    82944u    // [64][136] bf16
#define OFF_WLO    100352u
#define OFF_AWHI0  117760u   // [64][72] bf16
#define OFF_AWLO0  126976u
#define OFF_AWHI1  136192u
#define OFF_AWLO1  145408u
#define OFF_LOG0   154624u   // [64][68] fp32
#define OFF_LOG1   172032u
#define OFF_BIAS   189440u
#define OFF_RED    189696u   // 256 fp32
#define SMEM_BYTES 190720u

#define DXL 20736u
#define DWL 17408u
#define DAL 9216u

// named barrier ids (total participants = 384 for handoffs)
#define XID(p)  (2 + (p))     // conv(t) done -> G1(t) may read
#define LID(p)  ((p) ? 9 : 4) // G1(t) done -> softmax may read
#define AID(p)  ((p) ? 10 : 5)// softmax(t) done -> G2 may read
#define GID(p)  (6 + (p))     // G2(t) done -> buffers free
#define SBAR    8             // scalar-internal (128)

#define BARSYNC(id)    asm volatile("bar.sync %0, 384;"   :: "r"(id) : "memory")
#define BARARR(id)     asm volatile("bar.arrive %0, 384;" :: "r"(id) : "memory")
#define BARSYNC128(id) asm volatile("bar.sync %0, 128;"   :: "r"(id) : "memory")

// ---------------- scratch (deterministic split-K, no atomics) ---------------
__device__ float g_pv[(size_t)STRIPES * BB * KK * CC];
__device__ float g_pa[STRIPES * BB * KK];
__device__ float g_rss[BB * KK];

// ---------------- helpers ----------------
__device__ __forceinline__ uint32_t smem_u32(const void* p) {
    uint32_t a;
    asm("{ .reg .u64 t; cvta.to.shared.u64 t, %1; cvt.u32.u64 %0, t; }"
        : "=r"(a) : "l"(p));
    return a;
}
__device__ __forceinline__ void ldm4(uint32_t* r, uint32_t a) {
    asm volatile("ldmatrix.sync.aligned.m8n8.x4.shared.b16 {%0,%1,%2,%3}, [%4];"
                 : "=r"(r[0]), "=r"(r[1]), "=r"(r[2]), "=r"(r[3]) : "r"(a));
}
__device__ __forceinline__ void ldm4t(uint32_t* r, uint32_t a) {
    asm volatile("ldmatrix.sync.aligned.m8n8.x4.trans.shared.b16 {%0,%1,%2,%3}, [%4];"
                 : "=r"(r[0]), "=r"(r[1]), "=r"(r[2]), "=r"(r[3]) : "r"(a));
}
__device__ __forceinline__ void mma_bf16(float* d, const uint32_t* a, const uint32_t* b2) {
    asm volatile("mma.sync.aligned.m16n8k16.row.col.f32.bf16.bf16.f32 "
                 "{%0,%1,%2,%3}, {%4,%5,%6,%7}, {%8,%9}, {%0,%1,%2,%3};"
                 : "+f"(d[0]), "+f"(d[1]), "+f"(d[2]), "+f"(d[3])
                 : "r"(a[0]), "r"(a[1]), "r"(a[2]), "r"(a[3]), "r"(b2[0]), "r"(b2[1]));
}

// fast exp for v <= 0: pure FFMA/ALU, rel err ~2.4e-6
__device__ __forceinline__ float fast_exp_neg(float v) {
    float t = v * 1.4426950408889634f;
    t = fmaxf(t, -30.0f);
    float r  = t + 12582912.0f;
    float fi = r - 12582912.0f;
    float f  = t - fi;
    float p  = 0.0013333558146428443f;
    p = fmaf(p, f, 0.009618129107628477f);
    p = fmaf(p, f, 0.05550410866482158f);
    p = fmaf(p, f, 0.2402265069591007f);
    p = fmaf(p, f, 0.6931471805599453f);
    p = fmaf(p, f, 1.0f);
    int ei = (int)fi;
    return __int_as_float(__float_as_int(p) + (ei << 23));
}

__device__ __forceinline__ void split_pack4(const float* f, uint32_t* hi, uint32_t* lo) {
    uint16_t h[4], l[4];
    #pragma unroll
    for (int j = 0; j < 4; ++j) {
        __nv_bfloat16 hb = __float2bfloat16(f[j]);
        h[j] = __bfloat16_as_ushort(hb);
        l[j] = __bfloat16_as_ushort(__float2bfloat16(f[j] - __bfloat162float(hb)));
    }
    hi[0] = (uint32_t)h[0] | ((uint32_t)h[1] << 16);
    hi[1] = (uint32_t)h[2] | ((uint32_t)h[3] << 16);
    lo[0] = (uint32_t)l[0] | ((uint32_t)l[1] << 16);
    lo[1] = (uint32_t)l[2] | ((uint32_t)l[3] << 16);
}

// ---------------- warp-specialized fused kernel (8 MMA + 4 scalar warps) ----
__global__ __launch_bounds__(NTHREADS, 1)
void nv_ws_kernel(const float* __restrict__ x,
                  const float* __restrict__ conv_w,
                  const float* __restrict__ conv_b) {
    extern __shared__ char sm[];
    const uint32_t sb = smem_u32(sm);
    float* smf = (float*)sm;
    const int tid = threadIdx.x;
    const int lane = tid & 31;
    const int w = tid >> 5;
    const int b = blockIdx.y, stripe = blockIdx.x;

    // ---- init: W hi/lo, bias, ones rows (all threads) ----
    for (int i = tid; i < 2048; i += NTHREADS) {
        int k = i >> 5, c4 = (i & 31) * 4;
        float4 v = ((const float4*)conv_w)[i];
        float f[4] = {v.x, v.y, v.z, v.w};
        uint32_t hi[2], lo[2];
        split_pack4(f, hi, lo);
        uint32_t off = (uint32_t)(k * PW + c4) * 2;
        *(uint2*)(sm + OFF_WHI + off) = make_uint2(hi[0], hi[1]);
        *(uint2*)(sm + OFF_WLO + off) = make_uint2(lo[0], lo[1]);
    }
    if (tid < KK) smf[(OFF_BIAS >> 2) + tid] = conv_b[tid];
    for (int i = tid; i < 16 * PX; i += NTHREADS) {   // rows 128..143 both buffers
        int r = 128 + i / PX, c = i % PX;
        uint16_t hv = (r == 128) ? (uint16_t)0x3F80 : (uint16_t)0;
        uint32_t o = (uint32_t)(r * PX + c) * 2;
        *(uint16_t*)(sm + OFF_XHI0 + o) = hv;
        *(uint16_t*)(sm + OFF_XLO0 + o) = 0;
        *(uint16_t*)(sm + OFF_XHI1 + o) = hv;
        *(uint16_t*)(sm + OFF_XLO1 + o) = 0;
    }
    __syncthreads();

    const float* xb = x + (size_t)b * CC * NN;
    const int nbase = stripe * (NN / STRIPES);

    if (w < 8) {
        // ================= MMA group (warps 0-7, 2 per SMSP) =================
        const int wk = w & 1;          // 32-k block
        const int wq = w >> 1;         // G1: 16-n block / G2: 32-c block (0..3)

        float accV[2][4][4];           // [mf][c-8col j][frag]
        float accS[2][4];
        #pragma unroll
        for (int i = 0; i < 2; ++i) {
            #pragma unroll
            for (int j = 0; j < 4; ++j)
                #pragma unroll
                for (int r = 0; r < 4; ++r) accV[i][j][r] = 0.0f;
            #pragma unroll
            for (int r = 0; r < 4; ++r) accS[i][r] = 0.0f;
        }

        const uint32_t aA1 = sb + OFF_WHI + (uint32_t)((wk * 32 + (lane & 15)) * PBW) +
                             (uint32_t)((lane >> 4) * 16);
        const int rowL = wk * 32 + (lane >> 2);
        const int colL = wq * 16 + 2 * (lane & 3);

        // --- G1 for tile tt into LOG[tt&1] ---
        auto do_g1 = [&](int tt) {
            const int p = tt & 1;
            const uint32_t xbase = sb + (p ? OFF_XHI1 : OFF_XHI0);
            float* sLog = (float*)(sm + (p ? OFF_LOG1 : OFF_LOG0));
            float accL[2][2][4];
            #pragma unroll
            for (int i = 0; i < 2; ++i)
                #pragma unroll
                for (int j = 0; j < 2; ++j)
                    #pragma unroll
                    for (int r = 0; r < 4; ++r) accL[i][j][r] = 0.0f;
            const uint32_t aB1 = xbase + (uint32_t)((lane & 15) * PBX) +
                                 (uint32_t)((wq * 16 + ((lane >> 4) << 3)) * 2);
            #pragma unroll
            for (int ks = 0; ks < 8; ++ks) {
                uint32_t Ahi[2][4], Alo[2][4], Bhi[4], Blo[4];
                #pragma unroll
                for (int mf = 0; mf < 2; ++mf) {
                    uint32_t a = aA1 + (uint32_t)(mf * 16 * PBW + ks * 32);
                    ldm4(Ahi[mf], a);
                    ldm4(Alo[mf], a + DWL);
                }
                {
                    uint32_t a = aB1 + (uint32_t)(ks * 16 * PBX);
                    ldm4t(Bhi, a);
                    ldm4t(Blo, a + DXL);
                }
                #pragma unroll
                for (int mf = 0; mf < 2; ++mf)
                    #pragma unroll
                    for (int s = 0; s < 2; ++s) {
                        float* d = accL[mf][s];
                        mma_bf16(d, Ahi[mf], &Bhi[2 * s]);
                        mma_bf16(d, Ahi[mf], &Blo[2 * s]);
                        mma_bf16(d, Alo[mf], &Bhi[2 * s]);
                    }
            }
            #pragma unroll
            for (int mf = 0; mf < 2; ++mf)
                #pragma unroll
                for (int s = 0; s < 2; ++s) {
                    float* pp = sLog + (rowL + mf * 16) * PL + colL + s * 8;
                    *(float2*)pp = make_float2(accL[mf][s][0], accL[mf][s][1]);
                    *(float2*)(pp + 8 * PL) =
                        make_float2(accL[mf][s][2], accL[mf][s][3]);
                }
        };

        // --- G2 for tile tt, accumulate accV/accS ---
        auto do_g2 = [&](int tt) {
            const int p = tt & 1;
            const uint32_t xbase = sb + (p ? OFF_XHI1 : OFF_XHI0);
            const uint32_t awb = sb + (p ? OFF_AWHI1 : OFF_AWHI0);
            const uint32_t aA2 = awb + (uint32_t)((wk * 32 + (lane & 15)) * PBA) +
                                 (uint32_t)((lane >> 4) * 16);
            const uint32_t aB2 = xbase +
                                 (uint32_t)(((lane & 7) + ((lane >> 4) << 3)) * PBX) +
                                 (uint32_t)((lane & 8) * 2);
            #pragma unroll
            for (int ks = 0; ks < 4; ++ks) {
                uint32_t Ahi[2][4], Alo[2][4];
                #pragma unroll
                for (int mf = 0; mf < 2; ++mf) {
                    uint32_t a = aA2 + (uint32_t)(mf * 16 * PBA + ks * 32);
                    ldm4(Ahi[mf], a);
                    ldm4(Alo[mf], a + DAL);
                }
                #pragma unroll
                for (int cf = 0; cf < 2; ++cf) {
                    uint32_t a = aB2 + (uint32_t)((wq * 32 + cf * 16) * PBX + ks * 32);
                    uint32_t Bhi[4], Blo[4];
                    ldm4(Bhi, a);
                    ldm4(Blo, a + DXL);
                    #pragma unroll
                    for (int mf = 0; mf < 2; ++mf)
                        #pragma unroll
                        for (int s = 0; s < 2; ++s) {
                            float* d = accV[mf][cf * 2 + s];
                            mma_bf16(d, Ahi[mf], &Bhi[2 * s]);
                            mma_bf16(d, Ahi[mf], &Blo[2 * s]);
                            mma_bf16(d, Alo[mf], &Bhi[2 * s]);
                        }
                }
                if (wq == 3) {                    // asum via ones row c=128
                    uint32_t a = aB2 + (uint32_t)(128 * PBX + ks * 32);
                    uint32_t Bhi[4], Blo[4];
                    ldm4(Bhi, a);
                    ldm4(Blo, a + DXL);
                    #pragma unroll
                    for (int mf = 0; mf < 2; ++mf) {
                        float* d = accS[mf];
                        mma_bf16(d, Ahi[mf], &Bhi[0]);
                        mma_bf16(d, Ahi[mf], &Blo[0]);
                        mma_bf16(d, Alo[mf], &Bhi[0]);
                    }
                }
            }
        };

        // pipeline: prologue G1(0), then { G1(t+1) ; G2(t) }
        BARSYNC(XID(0));
        do_g1(0);
        BARARR(LID(0));
        for (int t = 0; t < NT; ++t) {
            if (t + 1 < NT) {
                BARSYNC(XID((t + 1) & 1));
                do_g1(t + 1);
                BARARR(LID((t + 1) & 1));
            }
            BARSYNC(AID(t & 1));
            do_g2(t);
            if (t + 2 < NT) BARARR(GID(t & 1));
        }

        // ---- epilogue: write partial vlad + asum ----
        float* pv = g_pv + ((size_t)(stripe * BB + b)) * KK * CC;
        #pragma unroll
        for (int mf = 0; mf < 2; ++mf)
            #pragma unroll
            for (int j = 0; j < 4; ++j) {
                int k = wk * 32 + mf * 16 + (lane >> 2);
                int c = wq * 32 + j * 8 + 2 * (lane & 3);
                *(float2*)&pv[k * CC + c] =
                    make_float2(accV[mf][j][0], accV[mf][j][1]);
                *(float2*)&pv[(k + 8) * CC + c] =
                    make_float2(accV[mf][j][2], accV[mf][j][3]);
            }
        if (wq == 3 && (lane & 3) == 0) {
            float* pa = g_pa + (stripe * BB + b) * KK;
            #pragma unroll
            for (int mf = 0; mf < 2; ++mf) {
                int k = wk * 32 + mf * 16 + (lane >> 2);
                pa[k] = accS[mf][0];
                pa[k + 8] = accS[mf][2];
            }
        }
    } else {
        // ================= scalar group (warps 8-11) =================
        const int st = tid - 256;       // 0..127
        const int half = st >> 6;       // softmax k-half
        const int col = st & 63;        // softmax column
        float* sRed = smf + (OFF_RED >> 2);
        float* sBias = smf + (OFF_BIAS >> 2);

        auto conv_tile = [&](int tt) {
            const int p = tt & 1;
            const uint32_t dsthi = (p ? OFF_XHI1 : OFF_XHI0) + (uint32_t)(st * PBX);
            const float4* src =
                (const float4*)(xb + (size_t)st * NN + nbase + tt * TILE_N);
            #pragma unroll
            for (int j = 0; j < 16; ++j) {
                float4 v = src[j];
                float f[4] = {v.x, v.y, v.z, v.w};
                uint32_t hi[2], lo[2];
                split_pack4(f, hi, lo);
                *(uint2*)(sm + dsthi + j * 8) = make_uint2(hi[0], hi[1]);
                *(uint2*)(sm + dsthi + DXL + j * 8) = make_uint2(lo[0], lo[1]);
            }
        };

        conv_tile(0);
        BARARR(XID(0));
        conv_tile(1);
        BARARR(XID(1));

        for (int t = 0; t < NT; ++t) {
            const int p = t & 1;
            BARSYNC(LID(p));
            // softmax(relu(logits + bias)) over k for column col
            {
                float* sLog = (float*)(sm + (p ? OFF_LOG1 : OFF_LOG0));
                float l[32];
                float mx = 0.0f;
                #pragma unroll
                for (int i = 0; i < 32; ++i) {
                    float lv = sLog[(half * 32 + i) * PL + col] + sBias[half * 32 + i];
                    lv = fmaxf(lv, 0.0f);
                    l[i] = lv;
                    mx = fmaxf(mx, lv);
                }
                sRed[half * 64 + col] = mx;
                BARSYNC128(SBAR);
                mx = fmaxf(sRed[col], sRed[64 + col]);
                float ssum = 0.0f;
                #pragma unroll
                for (int i = 0; i < 32; ++i) {
                    float e = fast_exp_neg(l[i] - mx);
                    l[i] = e;
                    ssum += e;
                }
                sRed[128 + half * 64 + col] = ssum;
                BARSYNC128(SBAR);
                float rinv = 1.0f / (sRed[128 + col] + sRed[192 + col]);
                const uint32_t awb = (p ? OFF_AWHI1 : OFF_AWHI0);
                #pragma unroll
                for (int i = 0; i < 32; ++i) {
                    float a = l[i] * rinv;
                    __nv_bfloat16 h = __float2bfloat16(a);
                    float lo = a - __bfloat162float(h);
                    uint32_t off = (uint32_t)((half * 32 + i) * PA + col) * 2;
                    *(uint16_t*)(sm + awb + off) = __bfloat16_as_ushort(h);
                    *(uint16_t*)(sm + awb + DAL + off) =
                        __bfloat16_as_ushort(__float2bfloat16(lo));
                }
            }
            BARARR(AID(p));
            if (t + 2 < NT) {
                BARSYNC(GID(p));
                conv_tile(t + 2);
                BARARR(XID(p));
            }
        }
    }
}

// ---------------- kernel 2: split-K reduce + centroid + intra-normalize -----
__global__ void nv_reduce_kernel(const float* __restrict__ centroids,
                                 float* __restrict__ out) {
    const int k = blockIdx.x, b = blockIdx.y, c = threadIdx.x;  // 128 threads
    float v = 0.0f;
    #pragma unroll
    for (int s = 0; s < STRIPES; s++)
        v += g_pv[(((size_t)s * BB + b) * KK + k) * CC + c];
    float as = 0.0f;
    #pragma unroll
    for (int s = 0; s < STRIPES; s++)
        as += g_pa[(s * BB + b) * KK + k];
    v -= as * centroids[k * CC + c];

    float ss = v * v;
    #pragma unroll
    for (int o = 16; o > 0; o >>= 1)
        ss += __shfl_xor_sync(0xffffffffu, ss, o);
    __shared__ float red[4];
    const int warp = c >> 5, lane = c & 31;
    if (lane == 0) red[warp] = ss;
    __syncthreads();
    float tot = red[0] + red[1] + red[2] + red[3];
    float inv = 1.0f / fmaxf(sqrtf(tot), 1e-12f);
    out[((size_t)b * KK + k) * CC + c] = v * inv;
    if (c == 0) g_rss[b * KK + k] = tot * inv * inv;
}

// ---------------- kernel 3: global L2 normalize per batch -------------------
__global__ void nv_gnorm_kernel(float* __restrict__ out) {
    const int b = blockIdx.y;
    __shared__ float ginv;
    if (threadIdx.x == 0) {
        float ss = 0.0f;
        #pragma unroll 8
        for (int k = 0; k < KK; k++) ss += g_rss[b * KK + k];
        ginv = 1.0f / fmaxf(sqrtf(ss), 1e-12f);
    }
    __syncthreads();
    int idx = b * KK * CC + blockIdx.x * 512 + threadIdx.x;
    out[idx] *= ginv;
}

// ---------------- launch -----------------------------------------------------
extern "C" void kernel_launch(void* const* d_in, const int* in_sizes, int n_in,
                              void* d_out, int out_size) {
    const float* x         = (const float*)d_in[0];  // (32,128,16384,1)
    const float* conv_w    = (const float*)d_in[1];  // (64,128)
    const float* conv_b    = (const float*)d_in[2];  // (64,)
    const float* centroids = (const float*)d_in[3];  // (64,128)
    float* out             = (float*)d_out;          // (32, 8192)

    cudaFuncSetAttribute((const void*)nv_ws_kernel,
                         cudaFuncAttributeMaxDynamicSharedMemorySize, SMEM_BYTES);
    nv_ws_kernel<<<dim3(STRIPES, BB), NTHREADS, SMEM_BYTES>>>(x, conv_w, conv_b);
    nv_reduce_kernel<<<dim3(KK, BB), 128>>>(centroids, out);
    nv_gnorm_kernel<<<dim3(16, BB), 512>>>(out);
}

// round 8
// speedup vs baseline: 1.0797x; 1.0797x over previous
#include <cuda_runtime.h>
#include <cuda_bf16.h>
#include <stdint.h>

// ---------------- problem constants ----------------
#define BB 32
#define CC 128
#define NN 16384
#define KK 64
#define TILE_N 64
#define STRIPES 4
#define NT ((NN / STRIPES) / TILE_N)   // 64 tiles per CTA
#define NTHREADS 384

// ---------------- smem layout ----------------
#define PX  72       // x tile pitch (elems); 144 B rows
#define PBX 144
#define PA  72
#define PBA 144
#define PL  68       // logits pitch (fp32)

#define XBUF(i)   ((uint32_t)(i) * 41472u)   // X ring: hi at +0, lo at +DXL
#define DXL       20736u
#define OFF_LOG0  124416u    // [64][68] fp32
#define OFF_LOG1  141824u
#define OFF_AWHI0 159232u    // [64][72] bf16; lo at +DAL
#define OFF_AWHI1 177664u
#define DAL       9216u
#define OFF_BIAS  196096u    // 64 fp32
#define OFF_RED   196352u    // 256 fp32
#define SMEM_BYTES 197376u

// ---------------- named barrier ids ----------------
#define XC(s)  (1 + (s))     // conv(t) done -> G1 may read X[t%3]
#define XFB(s) (4 + (s))     // G2(t) done  -> conv(t+3) may write X[t%3]
#define LG(p)  (7 + (p))     // G1(t) done  -> softmax may read LOG[t%2]
#define LF(p)  (9 + (p))     // softmax(t) read LOG -> G1(t+2) may write
#define AIDB(p) (11 + (p))   // softmax(t) done -> G2 may read AW[t%2]
#define AWF(p) (13 + (p))    // G2(t) done -> softmax(t+2) may write AW[t%2]
#define SBAR   15            // scalar-internal (128)

#define BARSYNC(id)    asm volatile("bar.sync %0, 256;"   :: "r"(id) : "memory")
#define BARARR(id)     asm volatile("bar.arrive %0, 256;" :: "r"(id) : "memory")
#define BARSYNC128(id) asm volatile("bar.sync %0, 128;"   :: "r"(id) : "memory")

// ---------------- scratch (deterministic split-K, no atomics) ---------------
__device__ float g_pv[(size_t)STRIPES * BB * KK * CC];
__device__ float g_pa[STRIPES * BB * KK];
__device__ float g_rss[BB * KK];

// ---------------- helpers ----------------
__device__ __forceinline__ uint32_t smem_u32(const void* p) {
    uint32_t a;
    asm("{ .reg .u64 t; cvta.to.shared.u64 t, %1; cvt.u32.u64 %0, t; }"
        : "=r"(a) : "l"(p));
    return a;
}
__device__ __forceinline__ void ldm4(uint32_t* r, uint32_t a) {
    asm volatile("ldmatrix.sync.aligned.m8n8.x4.shared.b16 {%0,%1,%2,%3}, [%4];"
                 : "=r"(r[0]), "=r"(r[1]), "=r"(r[2]), "=r"(r[3]) : "r"(a));
}
__device__ __forceinline__ void ldm4t(uint32_t* r, uint32_t a) {
    asm volatile("ldmatrix.sync.aligned.m8n8.x4.trans.shared.b16 {%0,%1,%2,%3}, [%4];"
                 : "=r"(r[0]), "=r"(r[1]), "=r"(r[2]), "=r"(r[3]) : "r"(a));
}
__device__ __forceinline__ void mma_bf16(float* d, const uint32_t* a, const uint32_t* b2) {
    asm volatile("mma.sync.aligned.m16n8k16.row.col.f32.bf16.bf16.f32 "
                 "{%0,%1,%2,%3}, {%4,%5,%6,%7}, {%8,%9}, {%0,%1,%2,%3};"
                 : "+f"(d[0]), "+f"(d[1]), "+f"(d[2]), "+f"(d[3])
                 : "r"(a[0]), "r"(a[1]), "r"(a[2]), "r"(a[3]), "r"(b2[0]), "r"(b2[1]));
}

// fast exp for v <= 0: pure FFMA/ALU, rel err ~2.4e-6
__device__ __forceinline__ float fast_exp_neg(float v) {
    float t = v * 1.4426950408889634f;
    t = fmaxf(t, -30.0f);
    float r  = t + 12582912.0f;
    float fi = r - 12582912.0f;
    float f  = t - fi;
    float p  = 0.0013333558146428443f;
    p = fmaf(p, f, 0.009618129107628477f);
    p = fmaf(p, f, 0.05550410866482158f);
    p = fmaf(p, f, 0.2402265069591007f);
    p = fmaf(p, f, 0.6931471805599453f);
    p = fmaf(p, f, 1.0f);
    int ei = (int)fi;
    return __int_as_float(__float_as_int(p) + (ei << 23));
}

__device__ __forceinline__ void split_pack4(const float* f, uint32_t* hi, uint32_t* lo) {
    uint16_t h[4], l[4];
    #pragma unroll
    for (int j = 0; j < 4; ++j) {
        __nv_bfloat16 hb = __float2bfloat16(f[j]);
        h[j] = __bfloat16_as_ushort(hb);
        l[j] = __bfloat16_as_ushort(__float2bfloat16(f[j] - __bfloat162float(hb)));
    }
    hi[0] = (uint32_t)h[0] | ((uint32_t)h[1] << 16);
    hi[1] = (uint32_t)h[2] | ((uint32_t)h[3] << 16);
    lo[0] = (uint32_t)l[0] | ((uint32_t)l[1] << 16);
    lo[1] = (uint32_t)l[2] | ((uint32_t)l[3] << 16);
}

__device__ __forceinline__ uint32_t pack2bf_hi(float a, float b) {
    return (uint32_t)__bfloat16_as_ushort(__float2bfloat16(a)) |
           ((uint32_t)__bfloat16_as_ushort(__float2bfloat16(b)) << 16);
}

// ---------------- dataflow-pipelined fused kernel ----------------
__global__ __launch_bounds__(NTHREADS, 1)
void nv_df_kernel(const float* __restrict__ x,
                  const float* __restrict__ conv_w,
                  const float* __restrict__ conv_b) {
    extern __shared__ char sm[];
    const uint32_t sb = smem_u32(sm);
    float* smf = (float*)sm;
    const int tid = threadIdx.x;
    const int lane = tid & 31;
    const int w = tid >> 5;
    const int b = blockIdx.y, stripe = blockIdx.x;

    // ---- init: bias + ones rows in all 3 X buffers ----
    if (tid < KK) smf[(OFF_BIAS >> 2) + tid] = conv_b[tid];
    for (int i = tid; i < 16 * PX; i += NTHREADS) {   // rows 128..143
        int r = 128 + i / PX, c = i % PX;
        uint16_t hv = (r == 128) ? (uint16_t)0x3F80 : (uint16_t)0;
        uint32_t o = (uint32_t)(r * PX + c) * 2;
        #pragma unroll
        for (int bu = 0; bu < 3; ++bu) {
            *(uint16_t*)(sm + XBUF(bu) + o) = hv;
            *(uint16_t*)(sm + XBUF(bu) + DXL + o) = 0;
        }
    }
    __syncthreads();

    const float* xb = x + (size_t)b * CC * NN;
    const int nbase = stripe * (NN / STRIPES);

    if (w < 4) {
        // ============ G1 group (warps 0-3): logits = W @ x ============
        const int krow0 = w * 16;
        // hoist W fragments (hi/lo) straight from GMEM in A-frag layout
        uint32_t Whi[8][4], Wlo[8][4];
        {
            const int r0 = krow0 + (lane >> 2);
            const int c0 = (lane & 3) * 2;
            #pragma unroll
            for (int ks = 0; ks < 8; ++ks)
                #pragma unroll
                for (int q = 0; q < 4; ++q) {
                    int rr = r0 + ((q & 1) ? 8 : 0);
                    int cc = ks * 16 + c0 + ((q & 2) ? 8 : 0);
                    float2 v = *(const float2*)&conv_w[rr * CC + cc];
                    __nv_bfloat16 h0 = __float2bfloat16(v.x);
                    __nv_bfloat16 h1 = __float2bfloat16(v.y);
                    Whi[ks][q] = (uint32_t)__bfloat16_as_ushort(h0) |
                                 ((uint32_t)__bfloat16_as_ushort(h1) << 16);
                    Wlo[ks][q] = (uint32_t)__bfloat16_as_ushort(
                                     __float2bfloat16(v.x - __bfloat162float(h0))) |
                                 ((uint32_t)__bfloat16_as_ushort(
                                     __float2bfloat16(v.y - __bfloat162float(h1))) << 16);
                }
        }
        const int rowL = krow0 + (lane >> 2);
        const int colL = 2 * (lane & 3);

        for (int t = 0; t < NT; ++t) {
            BARSYNC(XC(t % 3));
            if (t >= 2) BARSYNC(LF(t & 1));
            const uint32_t xbase = sb + XBUF(t % 3);
            float* sLog = (float*)(sm + ((t & 1) ? OFF_LOG1 : OFF_LOG0));
            const uint32_t aB1 = xbase + (uint32_t)((lane & 15) * PBX) +
                                 (uint32_t)(((lane >> 4) << 3) * 2);
            float accL[8][4];
            #pragma unroll
            for (int j = 0; j < 8; ++j)
                #pragma unroll
                for (int r = 0; r < 4; ++r) accL[j][r] = 0.0f;
            #pragma unroll
            for (int ks = 0; ks < 8; ++ks) {
                #pragma unroll
                for (int nf = 0; nf < 4; ++nf) {
                    uint32_t a = aB1 + (uint32_t)(ks * 16 * PBX + nf * 32);
                    uint32_t Bhi[4], Blo[4];
                    ldm4t(Bhi, a);
                    ldm4t(Blo, a + DXL);
                    #pragma unroll
                    for (int s = 0; s < 2; ++s) {
                        float* d = accL[nf * 2 + s];
                        mma_bf16(d, Whi[ks], &Bhi[2 * s]);
                        mma_bf16(d, Whi[ks], &Blo[2 * s]);
                        mma_bf16(d, Wlo[ks], &Bhi[2 * s]);
                    }
                }
            }
            #pragma unroll
            for (int j = 0; j < 8; ++j) {
                float* pp = sLog + rowL * PL + j * 8 + colL;
                *(float2*)pp = make_float2(accL[j][0], accL[j][1]);
                *(float2*)(pp + 8 * PL) = make_float2(accL[j][2], accL[j][3]);
            }
            BARARR(LG(t & 1));
        }
    } else if (w < 8) {
        // ============ G2 group (warps 4-7): vlad += aw @ x^T ============
        const int g2w = w - 4;
        const int cbase = g2w * 32;
        float accV[4][4][4];           // [mf(k16)][cf*2+s][frag]
        float accS[4][4];
        #pragma unroll
        for (int i = 0; i < 4; ++i) {
            #pragma unroll
            for (int j = 0; j < 4; ++j)
                #pragma unroll
                for (int r = 0; r < 4; ++r) accV[i][j][r] = 0.0f;
            #pragma unroll
            for (int r = 0; r < 4; ++r) accS[i][r] = 0.0f;
        }

        for (int t = 0; t < NT; ++t) {
            BARSYNC(AIDB(t & 1));
            const uint32_t xbase = sb + XBUF(t % 3);
            const uint32_t awb = sb + ((t & 1) ? OFF_AWHI1 : OFF_AWHI0);
            const uint32_t aA2 = awb + (uint32_t)(((lane & 15)) * PBA) +
                                 (uint32_t)((lane >> 4) * 16);
            const uint32_t aB2 = xbase +
                                 (uint32_t)(((lane & 7) + ((lane >> 4) << 3)) * PBX) +
                                 (uint32_t)((lane & 8) * 2);
            #pragma unroll
            for (int ks = 0; ks < 4; ++ks) {
                uint32_t Ahi[4][4], Alo[4][4];
                #pragma unroll
                for (int mf = 0; mf < 4; ++mf) {
                    uint32_t a = aA2 + (uint32_t)(mf * 16 * PBA + ks * 32);
                    ldm4(Ahi[mf], a);
                    ldm4(Alo[mf], a + DAL);
                }
                #pragma unroll
                for (int cf = 0; cf < 2; ++cf) {
                    uint32_t a = aB2 + (uint32_t)((cbase + cf * 16) * PBX + ks * 32);
                    uint32_t Bhi[4], Blo[4];
                    ldm4(Bhi, a);
                    ldm4(Blo, a + DXL);
                    #pragma unroll
                    for (int mf = 0; mf < 4; ++mf)
                        #pragma unroll
                        for (int s = 0; s < 2; ++s) {
                            float* d = accV[mf][cf * 2 + s];
                            mma_bf16(d, Ahi[mf], &Bhi[2 * s]);
                            mma_bf16(d, Ahi[mf], &Blo[2 * s]);
                            mma_bf16(d, Alo[mf], &Bhi[2 * s]);
                        }
                }
                if (g2w == 3) {                    // asum via ones row c=128
                    uint32_t a = aB2 + (uint32_t)(128 * PBX + ks * 32);
                    uint32_t Bhi[4];
                    ldm4(Bhi, a);                  // lo rows are zero
                    #pragma unroll
                    for (int mf = 0; mf < 4; ++mf) {
                        float* d = accS[mf];
                        mma_bf16(d, Ahi[mf], &Bhi[0]);
                        mma_bf16(d, Alo[mf], &Bhi[0]);
                    }
                }
            }
            BARARR(AWF(t & 1));
            BARARR(XFB(t % 3));
        }

        // ---- epilogue: write partial vlad + asum ----
        float* pv = g_pv + ((size_t)(stripe * BB + b)) * KK * CC;
        #pragma unroll
        for (int mf = 0; mf < 4; ++mf)
            #pragma unroll
            for (int j = 0; j < 4; ++j) {
                int k = mf * 16 + (lane >> 2);
                int c = cbase + j * 8 + 2 * (lane & 3);
                *(float2*)&pv[k * CC + c] =
                    make_float2(accV[mf][j][0], accV[mf][j][1]);
                *(float2*)&pv[(k + 8) * CC + c] =
                    make_float2(accV[mf][j][2], accV[mf][j][3]);
            }
        if (g2w == 3 && (lane & 3) == 0) {
            float* pa = g_pa + (stripe * BB + b) * KK;
            #pragma unroll
            for (int mf = 0; mf < 4; ++mf) {
                int k = mf * 16 + (lane >> 2);
                pa[k] = accS[mf][0];
                pa[k + 8] = accS[mf][2];
            }
        }
    } else {
        // ============ scalar group (warps 8-11): conv + softmax ============
        const int st = tid - 256;       // 0..127
        const int half = st >> 6;       // softmax k-half
        const int col = st & 63;        // softmax column
        float* sRed = smf + (OFF_RED >> 2);
        float* sBias = smf + (OFF_BIAS >> 2);

        auto conv_tile = [&](int tt) {
            const uint32_t dsthi = XBUF(tt % 3) + (uint32_t)(st * PBX);
            const float4* src =
                (const float4*)(xb + (size_t)st * NN + nbase + tt * TILE_N);
            #pragma unroll
            for (int j = 0; j < 16; ++j) {
                float4 v = src[j];
                float f[4] = {v.x, v.y, v.z, v.w};
                uint32_t hi[2], lo[2];
                split_pack4(f, hi, lo);
                *(uint2*)(sm + dsthi + j * 8) = make_uint2(hi[0], hi[1]);
                *(uint2*)(sm + dsthi + DXL + j * 8) = make_uint2(lo[0], lo[1]);
            }
        };

        conv_tile(0);
        BARARR(XC(0));
        conv_tile(1);
        BARARR(XC(1));

        for (int t = 0; t < NT; ++t) {
            const int p = t & 1;
            BARSYNC(LG(p));
            float* sLog = (float*)(sm + (p ? OFF_LOG1 : OFF_LOG0));
            float l[32];
            float mx = 0.0f;
            #pragma unroll
            for (int i = 0; i < 32; ++i) {
                float lv = sLog[(half * 32 + i) * PL + col] + sBias[half * 32 + i];
                lv = fmaxf(lv, 0.0f);
                l[i] = lv;
                mx = fmaxf(mx, lv);
            }
            sRed[half * 64 + col] = mx;
            BARSYNC128(SBAR);
            mx = fmaxf(sRed[col], sRed[64 + col]);
            float ssum = 0.0f;
            #pragma unroll
            for (int i = 0; i < 32; ++i) {
                float e = fast_exp_neg(l[i] - mx);
                l[i] = e;
                ssum += e;
            }
            BARARR(LF(p));                 // l[] consumed -> LOG free
            sRed[128 + half * 64 + col] = ssum;
            BARSYNC128(SBAR);
            float rinv = 1.0f / (sRed[128 + col] + sRed[192 + col]);
            if (t >= 2) BARSYNC(AWF(p));   // G2(t-2) done with AW[p]
            const uint32_t awb = (p ? OFF_AWHI1 : OFF_AWHI0);
            #pragma unroll
            for (int i = 0; i < 32; ++i) {
                float a = l[i] * rinv;
                __nv_bfloat16 h = __float2bfloat16(a);
                float lo = a - __bfloat162float(h);
                uint32_t off = (uint32_t)((half * 32 + i) * PA + col) * 2;
                *(uint16_t*)(sm + awb + off) = __bfloat16_as_ushort(h);
                *(uint16_t*)(sm + awb + DAL + off) =
                    __bfloat16_as_ushort(__float2bfloat16(lo));
            }
            BARARR(AIDB(p));
            if (t + 2 < NT) {
                if (t >= 1) BARSYNC(XFB((t + 2) % 3));  // G2(t-1) freed slot
                conv_tile(t + 2);
                BARARR(XC((t + 2) % 3));
            }
        }
    }
}

// ---------------- kernel 2: split-K reduce + centroid + intra-normalize -----
__global__ void nv_reduce_kernel(const float* __restrict__ centroids,
                                 float* __restrict__ out) {
    const int k = blockIdx.x, b = blockIdx.y, c = threadIdx.x;  // 128 threads
    float v = 0.0f;
    #pragma unroll
    for (int s = 0; s < STRIPES; s++)
        v += g_pv[(((size_t)s * BB + b) * KK + k) * CC + c];
    float as = 0.0f;
    #pragma unroll
    for (int s = 0; s < STRIPES; s++)
        as += g_pa[(s * BB + b) * KK + k];
    v -= as * centroids[k * CC + c];

    float ss = v * v;
    #pragma unroll
    for (int o = 16; o > 0; o >>= 1)
        ss += __shfl_xor_sync(0xffffffffu, ss, o);
    __shared__ float red[4];
    const int warp = c >> 5, lane = c & 31;
    if (lane == 0) red[warp] = ss;
    __syncthreads();
    float tot = red[0] + red[1] + red[2] + red[3];
    float inv = 1.0f / fmaxf(sqrtf(tot), 1e-12f);
    out[((size_t)b * KK + k) * CC + c] = v * inv;
    if (c == 0) g_rss[b * KK + k] = tot * inv * inv;
}

// ---------------- kernel 3: global L2 normalize per batch -------------------
__global__ void nv_gnorm_kernel(float* __restrict__ out) {
    const int b = blockIdx.y;
    __shared__ float ginv;
    if (threadIdx.x == 0) {
        float ss = 0.0f;
        #pragma unroll 8
        for (int k = 0; k < KK; k++) ss += g_rss[b * KK + k];
        ginv = 1.0f / fmaxf(sqrtf(ss), 1e-12f);
    }
    __syncthreads();
    int idx = b * KK * CC + blockIdx.x * 512 + threadIdx.x;
    out[idx] *= ginv;
}

// ---------------- launch -----------------------------------------------------
extern "C" void kernel_launch(void* const* d_in, const int* in_sizes, int n_in,
                              void* d_out, int out_size) {
    const float* x         = (const float*)d_in[0];  // (32,128,16384,1)
    const float* conv_w    = (const float*)d_in[1];  // (64,128)
    const float* conv_b    = (const float*)d_in[2];  // (64,)
    const float* centroids = (const float*)d_in[3];  // (64,128)
    float* out             = (float*)d_out;          // (32, 8192)

    cudaFuncSetAttribute((const void*)nv_df_kernel,
                         cudaFuncAttributeMaxDynamicSharedMemorySize, SMEM_BYTES);
    nv_df_kernel<<<dim3(STRIPES, BB), NTHREADS, SMEM_BYTES>>>(x, conv_w, conv_b);
    nv_reduce_kernel<<<dim3(KK, BB), 128>>>(centroids, out);
    nv_gnorm_kernel<<<dim3(16, BB), 512>>>(out);
}

// round 9
// speedup vs baseline: 1.1578x; 1.0724x over previous
#include <cuda_runtime.h>
#include <cuda_fp16.h>
#include <stdint.h>

// ---------------- problem constants ----------------
#define BB 32
#define CC 128
#define NN 16384
#define KK 64
#define TILE_N 64
#define STRIPES 4
#define NT ((NN / STRIPES) / TILE_N)   // 64 tiles per CTA
#define NTHREADS 384

// ---------------- smem layout ----------------
#define PX  72       // x tile pitch (elems); 144 B rows
#define PBX 144
#define PA  72
#define PBA 144
#define PL  68       // logits pitch (fp32)

#define XBUF(i)   ((uint32_t)(i) * 41472u)   // X ring: hi at +0, lo at +DXL
#define DXL       20736u
#define OFF_LOG0  124416u    // [64][68] fp32
#define OFF_LOG1  141824u
#define OFF_AWHI0 159232u    // [64][72] fp16 (single precision level now)
#define OFF_AWHI1 177664u
#define OFF_BIAS  196096u    // 64 fp32
#define OFF_RED   196352u    // 256 fp32
#define SMEM_BYTES 197376u

// ---------------- named barrier ids ----------------
#define XC(s)  (1 + (s))     // conv(t) done -> G1 may read X[t%3]
#define XFB(s) (4 + (s))     // G2(t) done  -> conv(t+3) may write X[t%3]
#define LG(p)  (7 + (p))     // G1(t) done  -> softmax may read LOG[t%2]
#define LF(p)  (9 + (p))     // softmax(t) read LOG -> G1(t+2) may write
#define AIDB(p) (11 + (p))   // softmax(t) done -> G2 may read AW[t%2]
#define AWF(p) (13 + (p))    // G2(t) done -> softmax(t+2) may write AW[t%2]
#define SBAR   15            // scalar-internal (128)

#define BARSYNC(id)    asm volatile("bar.sync %0, 256;"   :: "r"(id) : "memory")
#define BARARR(id)     asm volatile("bar.arrive %0, 256;" :: "r"(id) : "memory")
#define BARSYNC128(id) asm volatile("bar.sync %0, 128;"   :: "r"(id) : "memory")

// ---------------- scratch (deterministic split-K, no atomics) ---------------
__device__ float g_pv[(size_t)STRIPES * BB * KK * CC];
__device__ float g_pa[STRIPES * BB * KK];
__device__ float g_rss[BB * KK];

// ---------------- helpers ----------------
__device__ __forceinline__ uint32_t smem_u32(const void* p) {
    uint32_t a;
    asm("{ .reg .u64 t; cvta.to.shared.u64 t, %1; cvt.u32.u64 %0, t; }"
        : "=r"(a) : "l"(p));
    return a;
}
__device__ __forceinline__ void ldm4(uint32_t* r, uint32_t a) {
    asm volatile("ldmatrix.sync.aligned.m8n8.x4.shared.b16 {%0,%1,%2,%3}, [%4];"
                 : "=r"(r[0]), "=r"(r[1]), "=r"(r[2]), "=r"(r[3]) : "r"(a));
}
__device__ __forceinline__ void ldm4t(uint32_t* r, uint32_t a) {
    asm volatile("ldmatrix.sync.aligned.m8n8.x4.trans.shared.b16 {%0,%1,%2,%3}, [%4];"
                 : "=r"(r[0]), "=r"(r[1]), "=r"(r[2]), "=r"(r[3]) : "r"(a));
}
__device__ __forceinline__ void mma_f16(float* d, const uint32_t* a, const uint32_t* b2) {
    asm volatile("mma.sync.aligned.m16n8k16.row.col.f32.f16.f16.f32 "
                 "{%0,%1,%2,%3}, {%4,%5,%6,%7}, {%8,%9}, {%0,%1,%2,%3};"
                 : "+f"(d[0]), "+f"(d[1]), "+f"(d[2]), "+f"(d[3])
                 : "r"(a[0]), "r"(a[1]), "r"(a[2]), "r"(a[3]), "r"(b2[0]), "r"(b2[1]));
}

// fast exp for v <= 0: pure FFMA/ALU, rel err ~2.4e-6
__device__ __forceinline__ float fast_exp_neg(float v) {
    float t = v * 1.4426950408889634f;
    t = fmaxf(t, -30.0f);
    float r  = t + 12582912.0f;
    float fi = r - 12582912.0f;
    float f  = t - fi;
    float p  = 0.0013333558146428443f;
    p = fmaf(p, f, 0.009618129107628477f);
    p = fmaf(p, f, 0.05550410866482158f);
    p = fmaf(p, f, 0.2402265069591007f);
    p = fmaf(p, f, 0.6931471805599453f);
    p = fmaf(p, f, 1.0f);
    int ei = (int)fi;
    return __int_as_float(__float_as_int(p) + (ei << 23));
}

// fp32 -> fp16 hi/lo split, 4 at a time, packed as 2x u32
__device__ __forceinline__ void split_pack4(const float* f, uint32_t* hi, uint32_t* lo) {
    uint16_t h[4], l[4];
    #pragma unroll
    for (int j = 0; j < 4; ++j) {
        __half hb = __float2half_rn(f[j]);
        h[j] = __half_as_ushort(hb);
        l[j] = __half_as_ushort(__float2half_rn(f[j] - __half2float(hb)));
    }
    hi[0] = (uint32_t)h[0] | ((uint32_t)h[1] << 16);
    hi[1] = (uint32_t)h[2] | ((uint32_t)h[3] << 16);
    lo[0] = (uint32_t)l[0] | ((uint32_t)l[1] << 16);
    lo[1] = (uint32_t)l[2] | ((uint32_t)l[3] << 16);
}

// ---------------- dataflow-pipelined fused kernel ----------------
__global__ __launch_bounds__(NTHREADS, 1)
void nv_df_kernel(const float* __restrict__ x,
                  const float* __restrict__ conv_w,
                  const float* __restrict__ conv_b) {
    extern __shared__ char sm[];
    const uint32_t sb = smem_u32(sm);
    float* smf = (float*)sm;
    const int tid = threadIdx.x;
    const int lane = tid & 31;
    const int w = tid >> 5;
    const int b = blockIdx.y, stripe = blockIdx.x;

    // ---- init: bias + ones rows in all 3 X buffers ----
    if (tid < KK) smf[(OFF_BIAS >> 2) + tid] = conv_b[tid];
    for (int i = tid; i < 16 * PX; i += NTHREADS) {   // rows 128..143
        int r = 128 + i / PX, c = i % PX;
        uint16_t hv = (r == 128) ? (uint16_t)0x3C00 : (uint16_t)0;   // fp16 1.0
        uint32_t o = (uint32_t)(r * PX + c) * 2;
        #pragma unroll
        for (int bu = 0; bu < 3; ++bu) {
            *(uint16_t*)(sm + XBUF(bu) + o) = hv;
            *(uint16_t*)(sm + XBUF(bu) + DXL + o) = 0;
        }
    }
    __syncthreads();

    const float* xb = x + (size_t)b * CC * NN;
    const int nbase = stripe * (NN / STRIPES);

    if (w < 4) {
        // ============ G1 group (warps 0-3): logits = W @ x (3 fp16 products) ==
        const int krow0 = w * 16;
        uint32_t Whi[8][4], Wlo[8][4];
        {
            const int r0 = krow0 + (lane >> 2);
            const int c0 = (lane & 3) * 2;
            #pragma unroll
            for (int ks = 0; ks < 8; ++ks)
                #pragma unroll
                for (int q = 0; q < 4; ++q) {
                    int rr = r0 + ((q & 1) ? 8 : 0);
                    int cc = ks * 16 + c0 + ((q & 2) ? 8 : 0);
                    float2 v = *(const float2*)&conv_w[rr * CC + cc];
                    __half h0 = __float2half_rn(v.x);
                    __half h1 = __float2half_rn(v.y);
                    Whi[ks][q] = (uint32_t)__half_as_ushort(h0) |
                                 ((uint32_t)__half_as_ushort(h1) << 16);
                    Wlo[ks][q] = (uint32_t)__half_as_ushort(
                                     __float2half_rn(v.x - __half2float(h0))) |
                                 ((uint32_t)__half_as_ushort(
                                     __float2half_rn(v.y - __half2float(h1))) << 16);
                }
        }
        const int rowL = krow0 + (lane >> 2);
        const int colL = 2 * (lane & 3);

        for (int t = 0; t < NT; ++t) {
            BARSYNC(XC(t % 3));
            if (t >= 2) BARSYNC(LF(t & 1));
            const uint32_t xbase = sb + XBUF(t % 3);
            float* sLog = (float*)(sm + ((t & 1) ? OFF_LOG1 : OFF_LOG0));
            const uint32_t aB1 = xbase + (uint32_t)((lane & 15) * PBX) +
                                 (uint32_t)(((lane >> 4) << 3) * 2);
            float accL[8][4];
            #pragma unroll
            for (int j = 0; j < 8; ++j)
                #pragma unroll
                for (int r = 0; r < 4; ++r) accL[j][r] = 0.0f;
            #pragma unroll
            for (int ks = 0; ks < 8; ++ks) {
                #pragma unroll
                for (int nf = 0; nf < 4; ++nf) {
                    uint32_t a = aB1 + (uint32_t)(ks * 16 * PBX + nf * 32);
                    uint32_t Bhi[4], Blo[4];
                    ldm4t(Bhi, a);
                    ldm4t(Blo, a + DXL);
                    #pragma unroll
                    for (int s = 0; s < 2; ++s) {
                        float* d = accL[nf * 2 + s];
                        mma_f16(d, Whi[ks], &Bhi[2 * s]);
                        mma_f16(d, Whi[ks], &Blo[2 * s]);
                        mma_f16(d, Wlo[ks], &Bhi[2 * s]);
                    }
                }
            }
            #pragma unroll
            for (int j = 0; j < 8; ++j) {
                float* pp = sLog + rowL * PL + j * 8 + colL;
                *(float2*)pp = make_float2(accL[j][0], accL[j][1]);
                *(float2*)(pp + 8 * PL) = make_float2(accL[j][2], accL[j][3]);
            }
            BARARR(LG(t & 1));
        }
    } else if (w < 8) {
        // ============ G2 group (warps 4-7): vlad += a @ x^T (1 fp16 product) ==
        const int g2w = w - 4;
        const int cbase = g2w * 32;
        float accV[4][4][4];           // [mf(k16)][cf*2+s][frag]
        float accS[4][4];
        #pragma unroll
        for (int i = 0; i < 4; ++i) {
            #pragma unroll
            for (int j = 0; j < 4; ++j)
                #pragma unroll
                for (int r = 0; r < 4; ++r) accV[i][j][r] = 0.0f;
            #pragma unroll
            for (int r = 0; r < 4; ++r) accS[i][r] = 0.0f;
        }

        for (int t = 0; t < NT; ++t) {
            BARSYNC(AIDB(t & 1));
            const uint32_t xbase = sb + XBUF(t % 3);
            const uint32_t awb = sb + ((t & 1) ? OFF_AWHI1 : OFF_AWHI0);
            const uint32_t aA2 = awb + (uint32_t)(((lane & 15)) * PBA) +
                                 (uint32_t)((lane >> 4) * 16);
            const uint32_t aB2 = xbase +
                                 (uint32_t)(((lane & 7) + ((lane >> 4) << 3)) * PBX) +
                                 (uint32_t)((lane & 8) * 2);
            #pragma unroll
            for (int ks = 0; ks < 4; ++ks) {
                uint32_t Ahi[4][4];
                #pragma unroll
                for (int mf = 0; mf < 4; ++mf)
                    ldm4(Ahi[mf], aA2 + (uint32_t)(mf * 16 * PBA + ks * 32));
                #pragma unroll
                for (int cf = 0; cf < 2; ++cf) {
                    uint32_t a = aB2 + (uint32_t)((cbase + cf * 16) * PBX + ks * 32);
                    uint32_t Bhi[4];
                    ldm4(Bhi, a);
                    #pragma unroll
                    for (int mf = 0; mf < 4; ++mf)
                        #pragma unroll
                        for (int s = 0; s < 2; ++s)
                            mma_f16(accV[mf][cf * 2 + s], Ahi[mf], &Bhi[2 * s]);
                }
                if (g2w == 3) {                    // asum via ones row c=128
                    uint32_t a = aB2 + (uint32_t)(128 * PBX + ks * 32);
                    uint32_t Bhi[4];
                    ldm4(Bhi, a);
                    #pragma unroll
                    for (int mf = 0; mf < 4; ++mf)
                        mma_f16(accS[mf], Ahi[mf], &Bhi[0]);
                }
            }
            BARARR(AWF(t & 1));
            BARARR(XFB(t % 3));
        }

        // ---- epilogue: write partial vlad + asum ----
        float* pv = g_pv + ((size_t)(stripe * BB + b)) * KK * CC;
        #pragma unroll
        for (int mf = 0; mf < 4; ++mf)
            #pragma unroll
            for (int j = 0; j < 4; ++j) {
                int k = mf * 16 + (lane >> 2);
                int c = cbase + j * 8 + 2 * (lane & 3);
                *(float2*)&pv[k * CC + c] =
                    make_float2(accV[mf][j][0], accV[mf][j][1]);
                *(float2*)&pv[(k + 8) * CC + c] =
                    make_float2(accV[mf][j][2], accV[mf][j][3]);
            }
        if (g2w == 3 && (lane & 3) == 0) {
            float* pa = g_pa + (stripe * BB + b) * KK;
            #pragma unroll
            for (int mf = 0; mf < 4; ++mf) {
                int k = mf * 16 + (lane >> 2);
                pa[k] = accS[mf][0];
                pa[k + 8] = accS[mf][2];
            }
        }
    } else {
        // ============ scalar group (warps 8-11): conv + softmax ============
        const int st = tid - 256;       // 0..127
        const int half_ = st >> 6;      // softmax k-half
        const int col = st & 63;        // softmax column
        float* sRed = smf + (OFF_RED >> 2);
        float* sBias = smf + (OFF_BIAS >> 2);

        auto conv_tile = [&](int tt) {
            const uint32_t dsthi = XBUF(tt % 3) + (uint32_t)(st * PBX);
            const float4* src =
                (const float4*)(xb + (size_t)st * NN + nbase + tt * TILE_N);
            #pragma unroll
            for (int j = 0; j < 16; ++j) {
                float4 v = src[j];
                float f[4] = {v.x, v.y, v.z, v.w};
                uint32_t hi[2], lo[2];
                split_pack4(f, hi, lo);
                *(uint2*)(sm + dsthi + j * 8) = make_uint2(hi[0], hi[1]);
                *(uint2*)(sm + dsthi + DXL + j * 8) = make_uint2(lo[0], lo[1]);
            }
        };

        conv_tile(0);
        BARARR(XC(0));
        conv_tile(1);
        BARARR(XC(1));

        for (int t = 0; t < NT; ++t) {
            const int p = t & 1;
            BARSYNC(LG(p));
            float* sLog = (float*)(sm + (p ? OFF_LOG1 : OFF_LOG0));
            float l[32];
            float mx = 0.0f;
            #pragma unroll
            for (int i = 0; i < 32; ++i) {
                float lv = sLog[(half_ * 32 + i) * PL + col] + sBias[half_ * 32 + i];
                lv = fmaxf(lv, 0.0f);
                l[i] = lv;
                mx = fmaxf(mx, lv);
            }
            sRed[half_ * 64 + col] = mx;
            BARSYNC128(SBAR);
            mx = fmaxf(sRed[col], sRed[64 + col]);
            float ssum = 0.0f;
            #pragma unroll
            for (int i = 0; i < 32; ++i) {
                float e = fast_exp_neg(l[i] - mx);
                l[i] = e;
                ssum += e;
            }
            BARARR(LF(p));                 // l[] consumed -> LOG free
            sRed[128 + half_ * 64 + col] = ssum;
            BARSYNC128(SBAR);
            float rinv = 1.0f / (sRed[128 + col] + sRed[192 + col]);
            if (t >= 2) BARSYNC(AWF(p));   // G2(t-2) done with AW[p]
            const uint32_t awb = (p ? OFF_AWHI1 : OFF_AWHI0);
            #pragma unroll
            for (int i = 0; i < 32; ++i) {
                float a = l[i] * rinv;
                uint32_t off = (uint32_t)((half_ * 32 + i) * PA + col) * 2;
                *(uint16_t*)(sm + awb + off) =
                    __half_as_ushort(__float2half_rn(a));
            }
            BARARR(AIDB(p));
            if (t + 2 < NT) {
                if (t >= 1) BARSYNC(XFB((t + 2) % 3));  // G2(t-1) freed slot
                conv_tile(t + 2);
                BARARR(XC((t + 2) % 3));
            }
        }
    }
}

// ---------------- kernel 2: split-K reduce + centroid + intra-normalize -----
__global__ void nv_reduce_kernel(const float* __restrict__ centroids,
                                 float* __restrict__ out) {
    const int k = blockIdx.x, b = blockIdx.y, c = threadIdx.x;  // 128 threads
    float v = 0.0f;
    #pragma unroll
    for (int s = 0; s < STRIPES; s++)
        v += g_pv[(((size_t)s * BB + b) * KK + k) * CC + c];
    float as = 0.0f;
    #pragma unroll
    for (int s = 0; s < STRIPES; s++)
        as += g_pa[(s * BB + b) * KK + k];
    v -= as * centroids[k * CC + c];

    float ss = v * v;
    #pragma unroll
    for (int o = 16; o > 0; o >>= 1)
        ss += __shfl_xor_sync(0xffffffffu, ss, o);
    __shared__ float red[4];
    const int warp = c >> 5, lane = c & 31;
    if (lane == 0) red[warp] = ss;
    __syncthreads();
    float tot = red[0] + red[1] + red[2] + red[3];
    float inv = 1.0f / fmaxf(sqrtf(tot), 1e-12f);
    out[((size_t)b * KK + k) * CC + c] = v * inv;
    if (c == 0) g_rss[b * KK + k] = tot * inv * inv;
}

// ---------------- kernel 3: global L2 normalize per batch -------------------
__global__ void nv_gnorm_kernel(float* __restrict__ out) {
    const int b = blockIdx.y;
    __shared__ float ginv;
    if (threadIdx.x == 0) {
        float ss = 0.0f;
        #pragma unroll 8
        for (int k = 0; k < KK; k++) ss += g_rss[b * KK + k];
        ginv = 1.0f / fmaxf(sqrtf(ss), 1e-12f);
    }
    __syncthreads();
    int idx = b * KK * CC + blockIdx.x * 512 + threadIdx.x;
    out[idx] *= ginv;
}

// ---------------- launch -----------------------------------------------------
extern "C" void kernel_launch(void* const* d_in, const int* in_sizes, int n_in,
                              void* d_out, int out_size) {
    const float* x         = (const float*)d_in[0];  // (32,128,16384,1)
    const float* conv_w    = (const float*)d_in[1];  // (64,128)
    const float* conv_b    = (const float*)d_in[2];  // (64,)
    const float* centroids = (const float*)d_in[3];  // (64,128)
    float* out             = (float*)d_out;          // (32, 8192)

    cudaFuncSetAttribute((const void*)nv_df_kernel,
                         cudaFuncAttributeMaxDynamicSharedMemorySize, SMEM_BYTES);
    nv_df_kernel<<<dim3(STRIPES, BB), NTHREADS, SMEM_BYTES>>>(x, conv_w, conv_b);
    nv_reduce_kernel<<<dim3(KK, BB), 128>>>(centroids, out);
    nv_gnorm_kernel<<<dim3(16, BB), 512>>>(out);
}

// round 10
// speedup vs baseline: 1.4906x; 1.2875x over previous
#include <cuda_runtime.h>
#include <cuda_fp16.h>
#include <stdint.h>

// ---------------- problem constants ----------------
#define BB 32
#define CC 128
#define NN 16384
#define KK 64
#define TILE_N 64
#define STRIPES 4
#define NT ((NN / STRIPES) / TILE_N)   // 64 tiles per CTA
#define NTHREADS 384

// ---------------- smem layout ----------------
#define PX  72       // x tile pitch (elems); 144 B rows
#define PBX 144
#define PA  72
#define PBA 144
#define PL  68       // logits pitch (fp32)

#define XBUF(i)   ((uint32_t)(i) * 20736u)   // X ring (fp16 hi only), 3 deep
#define OFF_LOG0  62208u     // [64][68] fp32
#define OFF_LOG1  79616u
#define OFF_AWHI0 97024u     // [64][72] fp16
#define OFF_AWHI1 106240u
#define OFF_BIAS  115456u    // 64 fp32
#define OFF_RED   115712u    // 256 fp32
#define SMEM_BYTES 116736u

// ---------------- named barrier ids ----------------
#define XC(s)  (1 + (s))     // conv(t) done -> G1 may read X[t%3]
#define XFB(s) (4 + (s))     // G2(t) done  -> conv(t+3) may write X[t%3]
#define LG(p)  (7 + (p))     // G1(t) done  -> softmax may read LOG[t%2]
#define LF(p)  (9 + (p))     // softmax(t) read LOG -> G1(t+2) may write
#define AIDB(p) (11 + (p))   // softmax(t) done -> G2 may read AW[t%2]
#define AWF(p) (13 + (p))    // G2(t) done -> softmax(t+2) may write AW[t%2]
#define SBAR   15            // scalar-internal (128)

#define BARSYNC(id)    asm volatile("bar.sync %0, 256;"   :: "r"(id) : "memory")
#define BARARR(id)     asm volatile("bar.arrive %0, 256;" :: "r"(id) : "memory")
#define BARSYNC128(id) asm volatile("bar.sync %0, 128;"   :: "r"(id) : "memory")

// ---------------- scratch (deterministic split-K, no atomics) ---------------
__device__ float g_pv[(size_t)STRIPES * BB * KK * CC];
__device__ float g_pa[STRIPES * BB * KK];
__device__ float g_rss[BB * KK];

// ---------------- helpers ----------------
__device__ __forceinline__ uint32_t smem_u32(const void* p) {
    uint32_t a;
    asm("{ .reg .u64 t; cvta.to.shared.u64 t, %1; cvt.u32.u64 %0, t; }"
        : "=r"(a) : "l"(p));
    return a;
}
__device__ __forceinline__ void ldm4(uint32_t* r, uint32_t a) {
    asm volatile("ldmatrix.sync.aligned.m8n8.x4.shared.b16 {%0,%1,%2,%3}, [%4];"
                 : "=r"(r[0]), "=r"(r[1]), "=r"(r[2]), "=r"(r[3]) : "r"(a));
}
__device__ __forceinline__ void ldm4t(uint32_t* r, uint32_t a) {
    asm volatile("ldmatrix.sync.aligned.m8n8.x4.trans.shared.b16 {%0,%1,%2,%3}, [%4];"
                 : "=r"(r[0]), "=r"(r[1]), "=r"(r[2]), "=r"(r[3]) : "r"(a));
}
__device__ __forceinline__ void mma_f16(float* d, const uint32_t* a, const uint32_t* b2) {
    asm volatile("mma.sync.aligned.m16n8k16.row.col.f32.f16.f16.f32 "
                 "{%0,%1,%2,%3}, {%4,%5,%6,%7}, {%8,%9}, {%0,%1,%2,%3};"
                 : "+f"(d[0]), "+f"(d[1]), "+f"(d[2]), "+f"(d[3])
                 : "r"(a[0]), "r"(a[1]), "r"(a[2]), "r"(a[3]), "r"(b2[0]), "r"(b2[1]));
}

// fast exp for v <= 0: pure FFMA/ALU, rel err ~2.4e-6
__device__ __forceinline__ float fast_exp_neg(float v) {
    float t = v * 1.4426950408889634f;
    t = fmaxf(t, -30.0f);
    float r  = t + 12582912.0f;
    float fi = r - 12582912.0f;
    float f  = t - fi;
    float p  = 0.0013333558146428443f;
    p = fmaf(p, f, 0.009618129107628477f);
    p = fmaf(p, f, 0.05550410866482158f);
    p = fmaf(p, f, 0.2402265069591007f);
    p = fmaf(p, f, 0.6931471805599453f);
    p = fmaf(p, f, 1.0f);
    int ei = (int)fi;
    return __int_as_float(__float_as_int(p) + (ei << 23));
}

// ---------------- dataflow-pipelined fused kernel ----------------
__global__ __launch_bounds__(NTHREADS, 1)
void nv_df_kernel(const float* __restrict__ x,
                  const float* __restrict__ conv_w,
                  const float* __restrict__ conv_b) {
    extern __shared__ char sm[];
    const uint32_t sb = smem_u32(sm);
    float* smf = (float*)sm;
    const int tid = threadIdx.x;
    const int lane = tid & 31;
    const int w = tid >> 5;
    const int b = blockIdx.y, stripe = blockIdx.x;

    // ---- init: bias + ones rows in all 3 X buffers ----
    if (tid < KK) smf[(OFF_BIAS >> 2) + tid] = conv_b[tid];
    for (int i = tid; i < 16 * PX; i += NTHREADS) {   // rows 128..143
        int r = 128 + i / PX, c = i % PX;
        uint16_t hv = (r == 128) ? (uint16_t)0x3C00 : (uint16_t)0;   // fp16 1.0
        uint32_t o = (uint32_t)(r * PX + c) * 2;
        #pragma unroll
        for (int bu = 0; bu < 3; ++bu)
            *(uint16_t*)(sm + XBUF(bu) + o) = hv;
    }
    __syncthreads();

    const float* xb = x + (size_t)b * CC * NN;
    const int nbase = stripe * (NN / STRIPES);

    if (w < 4) {
        // ====== G1 group (warps 0-3): logits = (Whi + Wlo) @ x_hi ======
        const int krow0 = w * 16;
        uint32_t Whi[8][4], Wlo[8][4];
        {
            const int r0 = krow0 + (lane >> 2);
            const int c0 = (lane & 3) * 2;
            #pragma unroll
            for (int ks = 0; ks < 8; ++ks)
                #pragma unroll
                for (int q = 0; q < 4; ++q) {
                    int rr = r0 + ((q & 1) ? 8 : 0);
                    int cc = ks * 16 + c0 + ((q & 2) ? 8 : 0);
                    float2 v = *(const float2*)&conv_w[rr * CC + cc];
                    __half h0 = __float2half_rn(v.x);
                    __half h1 = __float2half_rn(v.y);
                    Whi[ks][q] = (uint32_t)__half_as_ushort(h0) |
                                 ((uint32_t)__half_as_ushort(h1) << 16);
                    Wlo[ks][q] = (uint32_t)__half_as_ushort(
                                     __float2half_rn(v.x - __half2float(h0))) |
                                 ((uint32_t)__half_as_ushort(
                                     __float2half_rn(v.y - __half2float(h1))) << 16);
                }
        }
        const int rowL = krow0 + (lane >> 2);
        const int colL = 2 * (lane & 3);

        for (int t = 0; t < NT; ++t) {
            BARSYNC(XC(t % 3));
            if (t >= 2) BARSYNC(LF(t & 1));
            const uint32_t xbase = sb + XBUF(t % 3);
            float* sLog = (float*)(sm + ((t & 1) ? OFF_LOG1 : OFF_LOG0));
            const uint32_t aB1 = xbase + (uint32_t)((lane & 15) * PBX) +
                                 (uint32_t)(((lane >> 4) << 3) * 2);
            float accL[8][4];
            #pragma unroll
            for (int j = 0; j < 8; ++j)
                #pragma unroll
                for (int r = 0; r < 4; ++r) accL[j][r] = 0.0f;
            #pragma unroll
            for (int ks = 0; ks < 8; ++ks) {
                #pragma unroll
                for (int nf = 0; nf < 4; ++nf) {
                    uint32_t a = aB1 + (uint32_t)(ks * 16 * PBX + nf * 32);
                    uint32_t Bhi[4];
                    ldm4t(Bhi, a);
                    #pragma unroll
                    for (int s = 0; s < 2; ++s) {
                        float* d = accL[nf * 2 + s];
                        mma_f16(d, Whi[ks], &Bhi[2 * s]);
                        mma_f16(d, Wlo[ks], &Bhi[2 * s]);
                    }
                }
            }
            #pragma unroll
            for (int j = 0; j < 8; ++j) {
                float* pp = sLog + rowL * PL + j * 8 + colL;
                *(float2*)pp = make_float2(accL[j][0], accL[j][1]);
                *(float2*)(pp + 8 * PL) = make_float2(accL[j][2], accL[j][3]);
            }
            BARARR(LG(t & 1));
        }
    } else if (w < 8) {
        // ====== G2 group (warps 4-7): vlad += a @ x_hi^T (1 product) ======
        const int g2w = w - 4;
        const int cbase = g2w * 32;
        float accV[4][4][4];           // [mf(k16)][cf*2+s][frag]
        float accS[4][4];
        #pragma unroll
        for (int i = 0; i < 4; ++i) {
            #pragma unroll
            for (int j = 0; j < 4; ++j)
                #pragma unroll
                for (int r = 0; r < 4; ++r) accV[i][j][r] = 0.0f;
            #pragma unroll
            for (int r = 0; r < 4; ++r) accS[i][r] = 0.0f;
        }

        for (int t = 0; t < NT; ++t) {
            BARSYNC(AIDB(t & 1));
            const uint32_t xbase = sb + XBUF(t % 3);
            const uint32_t awb = sb + ((t & 1) ? OFF_AWHI1 : OFF_AWHI0);
            const uint32_t aA2 = awb + (uint32_t)(((lane & 15)) * PBA) +
                                 (uint32_t)((lane >> 4) * 16);
            const uint32_t aB2 = xbase +
                                 (uint32_t)(((lane & 7) + ((lane >> 4) << 3)) * PBX) +
                                 (uint32_t)((lane & 8) * 2);
            #pragma unroll
            for (int ks = 0; ks < 4; ++ks) {
                uint32_t Ahi[4][4];
                #pragma unroll
                for (int mf = 0; mf < 4; ++mf)
                    ldm4(Ahi[mf], aA2 + (uint32_t)(mf * 16 * PBA + ks * 32));
                #pragma unroll
                for (int cf = 0; cf < 2; ++cf) {
                    uint32_t a = aB2 + (uint32_t)((cbase + cf * 16) * PBX + ks * 32);
                    uint32_t Bhi[4];
                    ldm4(Bhi, a);
                    #pragma unroll
                    for (int mf = 0; mf < 4; ++mf)
                        #pragma unroll
                        for (int s = 0; s < 2; ++s)
                            mma_f16(accV[mf][cf * 2 + s], Ahi[mf], &Bhi[2 * s]);
                }
                if (g2w == 3) {                    // asum via ones row c=128
                    uint32_t a = aB2 + (uint32_t)(128 * PBX + ks * 32);
                    uint32_t Bhi[4];
                    ldm4(Bhi, a);
                    #pragma unroll
                    for (int mf = 0; mf < 4; ++mf)
                        mma_f16(accS[mf], Ahi[mf], &Bhi[0]);
                }
            }
            BARARR(AWF(t & 1));
            BARARR(XFB(t % 3));
        }

        // ---- epilogue: write partial vlad + asum ----
        float* pv = g_pv + ((size_t)(stripe * BB + b)) * KK * CC;
        #pragma unroll
        for (int mf = 0; mf < 4; ++mf)
            #pragma unroll
            for (int j = 0; j < 4; ++j) {
                int k = mf * 16 + (lane >> 2);
                int c = cbase + j * 8 + 2 * (lane & 3);
                *(float2*)&pv[k * CC + c] =
                    make_float2(accV[mf][j][0], accV[mf][j][1]);
                *(float2*)&pv[(k + 8) * CC + c] =
                    make_float2(accV[mf][j][2], accV[mf][j][3]);
            }
        if (g2w == 3 && (lane & 3) == 0) {
            float* pa = g_pa + (stripe * BB + b) * KK;
            #pragma unroll
            for (int mf = 0; mf < 4; ++mf) {
                int k = mf * 16 + (lane >> 2);
                pa[k] = accS[mf][0];
                pa[k + 8] = accS[mf][2];
            }
        }
    } else {
        // ====== scalar group (warps 8-11): conv + softmax ======
        const int st = tid - 256;       // 0..127
        const int half_ = st >> 6;      // softmax k-half
        const int col = st & 63;        // softmax column
        float* sRed = smf + (OFF_RED >> 2);
        float* sBias = smf + (OFF_BIAS >> 2);

        auto conv_tile = [&](int tt) {
            const uint32_t dsthi = XBUF(tt % 3) + (uint32_t)(st * PBX);
            const float4* src =
                (const float4*)(xb + (size_t)st * NN + nbase + tt * TILE_N);
            #pragma unroll
            for (int j = 0; j < 16; ++j) {
                float4 v = src[j];
                __half2 h01 = __floats2half2_rn(v.x, v.y);
                __half2 h23 = __floats2half2_rn(v.z, v.w);
                *(uint2*)(sm + dsthi + j * 8) = make_uint2(
                    *(uint32_t*)&h01, *(uint32_t*)&h23);
            }
        };

        conv_tile(0);
        BARARR(XC(0));
        conv_tile(1);
        BARARR(XC(1));

        for (int t = 0; t < NT; ++t) {
            const int p = t & 1;
            BARSYNC(LG(p));
            float* sLog = (float*)(sm + (p ? OFF_LOG1 : OFF_LOG0));
            float l[32];
            float mx = 0.0f;
            #pragma unroll
            for (int i = 0; i < 32; ++i) {
                float lv = sLog[(half_ * 32 + i) * PL + col] + sBias[half_ * 32 + i];
                lv = fmaxf(lv, 0.0f);
                l[i] = lv;
                mx = fmaxf(mx, lv);
            }
            sRed[half_ * 64 + col] = mx;
            BARSYNC128(SBAR);
            mx = fmaxf(sRed[col], sRed[64 + col]);
            float ssum = 0.0f;
            #pragma unroll
            for (int i = 0; i < 32; ++i) {
                float e = fast_exp_neg(l[i] - mx);
                l[i] = e;
                ssum += e;
            }
            BARARR(LF(p));                 // l[] consumed -> LOG free
            sRed[128 + half_ * 64 + col] = ssum;
            BARSYNC128(SBAR);
            float rinv = 1.0f / (sRed[128 + col] + sRed[192 + col]);
            if (t >= 2) BARSYNC(AWF(p));   // G2(t-2) done with AW[p]
            const uint32_t awb = (p ? OFF_AWHI1 : OFF_AWHI0);
            #pragma unroll
            for (int i = 0; i < 32; ++i) {
                float a = l[i] * rinv;
                uint32_t off = (uint32_t)((half_ * 32 + i) * PA + col) * 2;
                *(uint16_t*)(sm + awb + off) =
                    __half_as_ushort(__float2half_rn(a));
            }
            BARARR(AIDB(p));
            if (t + 2 < NT) {
                if (t >= 1) BARSYNC(XFB((t + 2) % 3));  // G2(t-1) freed slot
                conv_tile(t + 2);
                BARARR(XC((t + 2) % 3));
            }
        }
    }
}

// ---------------- kernel 2: split-K reduce + centroid + intra-normalize -----
__global__ void nv_reduce_kernel(const float* __restrict__ centroids,
                                 float* __restrict__ out) {
    const int k = blockIdx.x, b = blockIdx.y, c = threadIdx.x;  // 128 threads
    float v = 0.0f;
    #pragma unroll
    for (int s = 0; s < STRIPES; s++)
        v += g_pv[(((size_t)s * BB + b) * KK + k) * CC + c];
    float as = 0.0f;
    #pragma unroll
    for (int s = 0; s < STRIPES; s++)
        as += g_pa[(s * BB + b) * KK + k];
    v -= as * centroids[k * CC + c];

    float ss = v * v;
    #pragma unroll
    for (int o = 16; o > 0; o >>= 1)
        ss += __shfl_xor_sync(0xffffffffu, ss, o);
    __shared__ float red[4];
    const int warp = c >> 5, lane = c & 31;
    if (lane == 0) red[warp] = ss;
    __syncthreads();
    float tot = red[0] + red[1] + red[2] + red[3];
    float inv = 1.0f / fmaxf(sqrtf(tot), 1e-12f);
    out[((size_t)b * KK + k) * CC + c] = v * inv;
    if (c == 0) g_rss[b * KK + k] = tot * inv * inv;
}

// ---------------- kernel 3: global L2 normalize per batch -------------------
__global__ void nv_gnorm_kernel(float* __restrict__ out) {
    const int b = blockIdx.y;
    __shared__ float ginv;
    if (threadIdx.x == 0) {
        float ss = 0.0f;
        #pragma unroll 8
        for (int k = 0; k < KK; k++) ss += g_rss[b * KK + k];
        ginv = 1.0f / fmaxf(sqrtf(ss), 1e-12f);
    }
    __syncthreads();
    int idx = b * KK * CC + blockIdx.x * 512 + threadIdx.x;
    out[idx] *= ginv;
}

// ---------------- launch -----------------------------------------------------
extern "C" void kernel_launch(void* const* d_in, const int* in_sizes, int n_in,
                              void* d_out, int out_size) {
    const float* x         = (const float*)d_in[0];  // (32,128,16384,1)
    const float* conv_w    = (const float*)d_in[1];  // (64,128)
    const float* conv_b    = (const float*)d_in[2];  // (64,)
    const float* centroids = (const float*)d_in[3];  // (64,128)
    float* out             = (float*)d_out;          // (32, 8192)

    cudaFuncSetAttribute((const void*)nv_df_kernel,
                         cudaFuncAttributeMaxDynamicSharedMemorySize, SMEM_BYTES);
    nv_df_kernel<<<dim3(STRIPES, BB), NTHREADS, SMEM_BYTES>>>(x, conv_w, conv_b);
    nv_reduce_kernel<<<dim3(KK, BB), 128>>>(centroids, out);
    nv_gnorm_kernel<<<dim3(16, BB), 512>>>(out);
}

// round 12
// speedup vs baseline: 1.5089x; 1.0123x over previous
#include <cuda_runtime.h>
#include <cuda_fp16.h>
#include <stdint.h>

// ---------------- problem constants ----------------
#define BB 32
#define CC 128
#define NN 16384
#define KK 64
#define TILE_N 64
#define STRIPES 4
#define NT ((NN / STRIPES) / TILE_N)   // 64 tiles per CTA
#define NTHREADS 384

// ---------------- smem layout ----------------
#define PX  72       // x tile pitch (elems); 144 B rows
#define PBX 144
#define PA  72
#define PBA 144
#define PL  68       // logits pitch (fp32)

#define XBUF(i)   ((uint32_t)(i) * 20736u)   // X ring (fp16 hi only), 3 deep
#define OFF_LOG0  62208u     // [64][68] fp32
#define OFF_LOG1  79616u
#define OFF_AWHI0 97024u     // [64][72] fp16
#define OFF_AWHI1 106240u
#define OFF_BIAS  115456u    // 64 fp32
#define OFF_RED   115712u    // 256 fp32
#define SMEM_BYTES 116736u

// ---------------- named barrier ids ----------------
#define XC(s)  (1 + (s))     // conv(t) done -> G1 may read X[t%3]
#define XFB(s) (4 + (s))     // G2(t) done  -> conv(t+3) may write X[t%3]
#define LG(p)  (7 + (p))     // G1(t) done  -> softmax may read LOG[t%2]
#define LF(p)  (9 + (p))     // softmax(t) read LOG -> G1(t+2) may write
#define AIDB(p) (11 + (p))   // softmax(t) done -> G2 may read AW[t%2]
#define AWF(p) (13 + (p))    // G2(t) read AW[t%2] -> softmax(t+2) may write
#define SBAR   15            // scalar-internal (128)

#define BARSYNC(id)    asm volatile("bar.sync %0, 256;"   :: "r"(id) : "memory")
#define BARARR(id)     asm volatile("bar.arrive %0, 256;" :: "r"(id) : "memory")
#define BARSYNC128(id) asm volatile("bar.sync %0, 128;"   :: "r"(id) : "memory")

// ---------------- scratch (deterministic split-K, no atomics) ---------------
__device__ float g_pv[(size_t)STRIPES * BB * KK * CC];
__device__ float g_pa[STRIPES * BB * KK];
__device__ float g_rss[BB * KK];

// ---------------- helpers ----------------
__device__ __forceinline__ uint32_t smem_u32(const void* p) {
    uint32_t a;
    asm("{ .reg .u64 t; cvta.to.shared.u64 t, %1; cvt.u32.u64 %0, t; }"
        : "=r"(a) : "l"(p));
    return a;
}
__device__ __forceinline__ void ldm4(uint32_t* r, uint32_t a) {
    asm volatile("ldmatrix.sync.aligned.m8n8.x4.shared.b16 {%0,%1,%2,%3}, [%4];"
                 : "=r"(r[0]), "=r"(r[1]), "=r"(r[2]), "=r"(r[3]) : "r"(a));
}
__device__ __forceinline__ void ldm4t(uint32_t* r, uint32_t a) {
    asm volatile("ldmatrix.sync.aligned.m8n8.x4.trans.shared.b16 {%0,%1,%2,%3}, [%4];"
                 : "=r"(r[0]), "=r"(r[1]), "=r"(r[2]), "=r"(r[3]) : "r"(a));
}
__device__ __forceinline__ void mma_f16(float* d, const uint32_t* a, const uint32_t* b2) {
    asm volatile("mma.sync.aligned.m16n8k16.row.col.f32.f16.f16.f32 "
                 "{%0,%1,%2,%3}, {%4,%5,%6,%7}, {%8,%9}, {%0,%1,%2,%3};"
                 : "+f"(d[0]), "+f"(d[1]), "+f"(d[2]), "+f"(d[3])
                 : "r"(a[0]), "r"(a[1]), "r"(a[2]), "r"(a[3]), "r"(b2[0]), "r"(b2[1]));
}

// fast exp for v <= 0: pure FFMA/ALU, rel err ~2.4e-6
__device__ __forceinline__ float fast_exp_neg(float v) {
    float t = v * 1.4426950408889634f;
    t = fmaxf(t, -30.0f);
    float r  = t + 12582912.0f;
    float fi = r - 12582912.0f;
    float f  = t - fi;
    float p  = 0.0013333558146428443f;
    p = fmaf(p, f, 0.009618129107628477f);
    p = fmaf(p, f, 0.05550410866482158f);
    p = fmaf(p, f, 0.2402265069591007f);
    p = fmaf(p, f, 0.6931471805599453f);
    p = fmaf(p, f, 1.0f);
    int ei = (int)fi;
    return __int_as_float(__float_as_int(p) + (ei << 23));
}

// ---------------- dataflow-pipelined fused kernel ----------------
__global__ __launch_bounds__(NTHREADS, 1)
void nv_df_kernel(const float* __restrict__ x,
                  const float* __restrict__ conv_w,
                  const float* __restrict__ conv_b) {
    extern __shared__ char sm[];
    const uint32_t sb = smem_u32(sm);
    float* smf = (float*)sm;
    const int tid = threadIdx.x;
    const int lane = tid & 31;
    const int w = tid >> 5;
    const int b = blockIdx.y, stripe = blockIdx.x;

    // ---- init: bias + ones rows in all 3 X buffers ----
    if (tid < KK) smf[(OFF_BIAS >> 2) + tid] = conv_b[tid];
    for (int i = tid; i < 16 * PX; i += NTHREADS) {   // rows 128..143
        int r = 128 + i / PX, c = i % PX;
        uint16_t hv = (r == 128) ? (uint16_t)0x3C00 : (uint16_t)0;   // fp16 1.0
        uint32_t o = (uint32_t)(r * PX + c) * 2;
        #pragma unroll
        for (int bu = 0; bu < 3; ++bu)
            *(uint16_t*)(sm + XBUF(bu) + o) = hv;
    }
    __syncthreads();

    const float* xb = x + (size_t)b * CC * NN;
    const int nbase = stripe * (NN / STRIPES);

    if (w < 4) {
        // ====== G1 group (warps 0-3): logits = Whi @ x_hi (1 product) ======
        const int krow0 = w * 16;
        uint32_t Whi[8][4];
        {
            const int r0 = krow0 + (lane >> 2);
            const int c0 = (lane & 3) * 2;
            #pragma unroll
            for (int ks = 0; ks < 8; ++ks)
                #pragma unroll
                for (int q = 0; q < 4; ++q) {
                    int rr = r0 + ((q & 1) ? 8 : 0);
                    int cc = ks * 16 + c0 + ((q & 2) ? 8 : 0);
                    float2 v = *(const float2*)&conv_w[rr * CC + cc];
                    __half2 h = __floats2half2_rn(v.x, v.y);
                    Whi[ks][q] = *(uint32_t*)&h;
                }
        }
        const int rowL = krow0 + (lane >> 2);
        const int colL = 2 * (lane & 3);

        for (int t = 0; t < NT; ++t) {
            BARSYNC(XC(t % 3));
            if (t >= 2) BARSYNC(LF(t & 1));
            const uint32_t xbase = sb + XBUF(t % 3);
            float* sLog = (float*)(sm + ((t & 1) ? OFF_LOG1 : OFF_LOG0));
            const uint32_t aB1 = xbase + (uint32_t)((lane & 15) * PBX) +
                                 (uint32_t)(((lane >> 4) << 3) * 2);
            float accL[8][4];
            #pragma unroll
            for (int j = 0; j < 8; ++j)
                #pragma unroll
                for (int r = 0; r < 4; ++r) accL[j][r] = 0.0f;
            #pragma unroll
            for (int ks = 0; ks < 8; ++ks)
                #pragma unroll
                for (int nf = 0; nf < 4; ++nf) {
                    uint32_t a = aB1 + (uint32_t)(ks * 16 * PBX + nf * 32);
                    uint32_t Bhi[4];
                    ldm4t(Bhi, a);
                    mma_f16(accL[nf * 2 + 0], Whi[ks], &Bhi[0]);
                    mma_f16(accL[nf * 2 + 1], Whi[ks], &Bhi[2]);
                }
            #pragma unroll
            for (int j = 0; j < 8; ++j) {
                float* pp = sLog + rowL * PL + j * 8 + colL;
                *(float2*)pp = make_float2(accL[j][0], accL[j][1]);
                *(float2*)(pp + 8 * PL) = make_float2(accL[j][2], accL[j][3]);
            }
            BARARR(LG(t & 1));
        }
    } else if (w < 8) {
        // ====== G2 group (warps 4-7): vlad += a @ x_hi^T (1 product) ======
        const int g2w = w - 4;
        const int cbase = g2w * 32;
        float accV[4][4][4];
        float accS[4][4];
        #pragma unroll
        for (int i = 0; i < 4; ++i) {
            #pragma unroll
            for (int j = 0; j < 4; ++j)
                #pragma unroll
                for (int r = 0; r < 4; ++r) accV[i][j][r] = 0.0f;
            #pragma unroll
            for (int r = 0; r < 4; ++r) accS[i][r] = 0.0f;
        }

        for (int t = 0; t < NT; ++t) {
            BARSYNC(AIDB(t & 1));
            const uint32_t xbase = sb + XBUF(t % 3);
            const uint32_t awb = sb + ((t & 1) ? OFF_AWHI1 : OFF_AWHI0);
            const uint32_t aA2 = awb + (uint32_t)(((lane & 15)) * PBA) +
                                 (uint32_t)((lane >> 4) * 16);
            const uint32_t aB2 = xbase +
                                 (uint32_t)(((lane & 7) + ((lane >> 4) << 3)) * PBX) +
                                 (uint32_t)((lane & 8) * 2);
            #pragma unroll
            for (int ks = 0; ks < 4; ++ks) {
                uint32_t Ahi[4][4];
                #pragma unroll
                for (int mf = 0; mf < 4; ++mf)
                    ldm4(Ahi[mf], aA2 + (uint32_t)(mf * 16 * PBA + ks * 32));
                #pragma unroll
                for (int cf = 0; cf < 2; ++cf) {
                    uint32_t a = aB2 + (uint32_t)((cbase + cf * 16) * PBX + ks * 32);
                    uint32_t Bhi[4];
                    ldm4(Bhi, a);
                    #pragma unroll
                    for (int mf = 0; mf < 4; ++mf)
                        #pragma unroll
                        for (int s = 0; s < 2; ++s)
                            mma_f16(accV[mf][cf * 2 + s], Ahi[mf], &Bhi[2 * s]);
                }
                if (g2w == 3) {                    // asum via ones row c=128
                    uint32_t a = aB2 + (uint32_t)(128 * PBX + ks * 32);
                    uint32_t Bhi[4];
                    ldm4(Bhi, a);
                    #pragma unroll
                    for (int mf = 0; mf < 4; ++mf)
                        mma_f16(accS[mf], Ahi[mf], &Bhi[0]);
                }
            }
            BARARR(AWF(t & 1));
            BARARR(XFB(t % 3));
        }

        // ---- epilogue: write partial vlad + asum ----
        float* pv = g_pv + ((size_t)(stripe * BB + b)) * KK * CC;
        #pragma unroll
        for (int mf = 0; mf < 4; ++mf)
            #pragma unroll
            for (int j = 0; j < 4; ++j) {
                int k = mf * 16 + (lane >> 2);
                int c = cbase + j * 8 + 2 * (lane & 3);
                *(float2*)&pv[k * CC + c] =
                    make_float2(accV[mf][j][0], accV[mf][j][1]);
                *(float2*)&pv[(k + 8) * CC + c] =
                    make_float2(accV[mf][j][2], accV[mf][j][3]);
            }
        if (g2w == 3 && (lane & 3) == 0) {
            float* pa = g_pa + (stripe * BB + b) * KK;
            #pragma unroll
            for (int mf = 0; mf < 4; ++mf) {
                int k = mf * 16 + (lane >> 2);
                pa[k] = accS[mf][0];
                pa[k + 8] = accS[mf][2];
            }
        }
    } else {
        // ====== scalar group (warps 8-11): conv + softmax ======
        const int st = tid - 256;       // 0..127
        const int half_ = st >> 6;      // softmax k-half
        const int col = st & 63;        // softmax column
        float* sRed = smf + (OFF_RED >> 2);
        float* sBias = smf + (OFF_BIAS >> 2);

        auto conv_tile = [&](int tt) {
            const uint32_t dsthi = XBUF(tt % 3) + (uint32_t)(st * PBX);
            const float4* src =
                (const float4*)(xb + (size_t)st * NN + nbase + tt * TILE_N);
            #pragma unroll
            for (int j = 0; j < 16; ++j) {
                float4 v = src[j];
                __half2 h01 = __floats2half2_rn(v.x, v.y);
                __half2 h23 = __floats2half2_rn(v.z, v.w);
                *(uint2*)(sm + dsthi + j * 8) = make_uint2(
                    *(uint32_t*)&h01, *(uint32_t*)&h23);
            }
        };

        conv_tile(0);
        BARARR(XC(0));
        conv_tile(1);
        BARARR(XC(1));

        for (int t = 0; t < NT; ++t) {
            const int p = t & 1;
            BARSYNC(LG(p));
            float* sLog = (float*)(sm + (p ? OFF_LOG1 : OFF_LOG0));
            float l[32];
            float mx = 0.0f;
            #pragma unroll
            for (int i = 0; i < 32; ++i) {
                float lv = sLog[(half_ * 32 + i) * PL + col] + sBias[half_ * 32 + i];
                lv = fmaxf(lv, 0.0f);
                l[i] = lv;
                mx = fmaxf(mx, lv);
            }
            sRed[half_ * 64 + col] = mx;
            BARSYNC128(SBAR);
            mx = fmaxf(sRed[col], sRed[64 + col]);
            float ssum = 0.0f;
            #pragma unroll
            for (int i = 0; i < 32; ++i) {
                float e = fast_exp_neg(l[i] - mx);
                l[i] = e;
                ssum += e;
            }
            BARARR(LF(p));                 // l[] consumed -> LOG free
            sRed[128 + half_ * 64 + col] = ssum;
            BARSYNC128(SBAR);
            float rinv = 1.0f / (sRed[128 + col] + sRed[192 + col]);
            if (t >= 2) BARSYNC(AWF(p));   // G2(t-2) done with AW[p]
            const uint32_t awb = (p ? OFF_AWHI1 : OFF_AWHI0);
            #pragma unroll
            for (int i = 0; i < 32; ++i) {
                float a = l[i] * rinv;
                uint32_t off = (uint32_t)((half_ * 32 + i) * PA + col) * 2;
                *(uint16_t*)(sm + awb + off) =
                    __half_as_ushort(__float2half_rn(a));
            }
            BARARR(AIDB(p));
            if (t + 2 < NT) {
                if (t >= 1) BARSYNC(XFB((t + 2) % 3));  // G2(t-1) freed slot
                conv_tile(t + 2);
                BARARR(XC((t + 2) % 3));
            }
        }
    }
}

// ---------------- kernel 2: split-K reduce + centroid + intra-normalize -----
__global__ void nv_reduce_kernel(const float* __restrict__ centroids,
                                 float* __restrict__ out) {
    const int k = blockIdx.x, b = blockIdx.y, c = threadIdx.x;  // 128 threads
    float v = 0.0f;
    #pragma unroll
    for (int s = 0; s < STRIPES; s++)
        v += g_pv[(((size_t)s * BB + b) * KK + k) * CC + c];
    float as = 0.0f;
    #pragma unroll
    for (int s = 0; s < STRIPES; s++)
        as += g_pa[(s * BB + b) * KK + k];
    v -= as * centroids[k * CC + c];

    float ss = v * v;
    #pragma unroll
    for (int o = 16; o > 0; o >>= 1)
        ss += __shfl_xor_sync(0xffffffffu, ss, o);
    __shared__ float red[4];
    const int warp = c >> 5, lane = c & 31;
    if (lane == 0) red[warp] = ss;
    __syncthreads();
    float tot = red[0] + red[1] + red[2] + red[3];
    float inv = 1.0f / fmaxf(sqrtf(tot), 1e-12f);
    out[((size_t)b * KK + k) * CC + c] = v * inv;
    if (c == 0) g_rss[b * KK + k] = tot * inv * inv;
}

// ---------------- kernel 3: global L2 normalize per batch -------------------
__global__ void nv_gnorm_kernel(float* __restrict__ out) {
    const int b = blockIdx.y;
    __shared__ float ginv;
    if (threadIdx.x == 0) {
        float ss = 0.0f;
        #pragma unroll 8
        for (int k = 0; k < KK; k++) ss += g_rss[b * KK + k];
        ginv = 1.0f / fmaxf(sqrtf(ss), 1e-12f);
    }
    __syncthreads();
    int idx = b * KK * CC + blockIdx.x * 512 + threadIdx.x;
    out[idx] *= ginv;
}

// ---------------- launch -----------------------------------------------------
extern "C" void kernel_launch(void* const* d_in, const int* in_sizes, int n_in,
                              void* d_out, int out_size) {
    const float* x         = (const float*)d_in[0];  // (32,128,16384,1)
    const float* conv_w    = (const float*)d_in[1];  // (64,128)
    const float* conv_b    = (const float*)d_in[2];  // (64,)
    const float* centroids = (const float*)d_in[3];  // (64,128)
    float* out             = (float*)d_out;          // (32, 8192)

    cudaFuncSetAttribute((const void*)nv_df_kernel,
                         cudaFuncAttributeMaxDynamicSharedMemorySize, SMEM_BYTES);
    nv_df_kernel<<<dim3(STRIPES, BB), NTHREADS, SMEM_BYTES>>>(x, conv_w, conv_b);
    nv_reduce_kernel<<<dim3(KK, BB), 128>>>(centroids, out);
    nv_gnorm_kernel<<<dim3(16, BB), 512>>>(out);
}